// round 7
// baseline (speedup 1.0000x reference)
#include <cuda_runtime.h>
#include <math.h>
#include <stdint.h>

// Problem constants
#define NN 64
#define TT 128
#define DD 512
#define HH 1024
#define G4 4096   // 4*H

// ---------------- scratch (device globals; no allocations) ----------------
__device__ __align__(16) float  g_Xa[(NN * TT) * G4];   // 128 MB: x@Wx + b
__device__ __align__(16) float  g_P[(NN * 16) * G4];    // 16 MB: packed [n][l][c][gate]
__device__ __align__(16) float  g_WhT[HH * G4];         // 16 MB: packed [k][c][gate]
__device__ __align__(16) float  g_A2[(NN * 16) * HH];   // 4 MB
__device__ __align__(16) float2 g_hdup[2][NN * HH];     // h dup (h,h), [parity][n][k]
__device__ float g_cbuf[2][NN * HH];
__device__ float g_scores[3][NN * 16];

// ---------------- helpers ----------------
__device__ __forceinline__ unsigned long long fma2(unsigned long long a,
                                                   unsigned long long b,
                                                   unsigned long long c) {
    unsigned long long d;
    asm("fma.rn.f32x2 %0, %1, %2, %3;" : "=l"(d) : "l"(a), "l"(b), "l"(c));
    return d;
}
__device__ __forceinline__ unsigned long long dup2(float v) {
    unsigned long long r;
    asm("mov.b64 %0, {%1, %1};" : "=l"(r) : "f"(v));
    return r;
}
__device__ __forceinline__ unsigned long long pack2(float lo, float hi) {
    unsigned long long r;
    asm("mov.b64 %0, {%1, %2};" : "=l"(r) : "f"(lo), "f"(hi));
    return r;
}
__device__ __forceinline__ float2 unpack2(unsigned long long v) {
    float2 f;
    asm("mov.b64 {%0, %1}, %2;" : "=f"(f.x), "=f"(f.y) : "l"(v));
    return f;
}
__device__ __forceinline__ uint32_t smem_u32(const void* p) {
    return (uint32_t)__cvta_generic_to_shared(p);
}
__device__ __forceinline__ void cp_async16(uint32_t dst, const void* src) {
    asm volatile("cp.async.cg.shared.global [%0], [%1], 16;" :: "r"(dst), "l"(src) : "memory");
}

// ---------------- weight packing ----------------
__global__ void __launch_bounds__(256) pack_wh_kernel(const float* __restrict__ Wh) {
    int idx = blockIdx.x * 256 + threadIdx.x;
    int k = idx >> 10;
    int c = idx & 1023;
    const float* row = Wh + k * G4;
    float4 v;
    v.x = row[c];
    v.y = row[1024 + c];
    v.z = row[2048 + c];
    v.w = row[3072 + c];
    *(float4*)&g_WhT[idx * 4] = v;
}

__global__ void __launch_bounds__(256) transposeA_kernel(const float* __restrict__ A) {
    int idx = blockIdx.x * 256 + threadIdx.x;
    int r = idx >> 10;
    int k = idx & 1023;
    int n = r >> 4;
    int l = r & 15;
    g_A2[idx] = A[((n << 10) + k) * 16 + l];
}

// ---------------- tiled SGEMM (unchanged; ~52% of fma2 peak) ----------------
template <int MODE>
__global__ void __launch_bounds__(256) sgemm_kernel(const float* __restrict__ Ain,
                                                    const float* __restrict__ B,
                                                    const float* __restrict__ bias,
                                                    int M, int N, int K) {
    __shared__ float As[16][128];
    __shared__ float Bs[16][64];

    const float* Amat = (MODE == 1) ? (const float*)g_A2 : Ain;
    float* C = (MODE == 1) ? (float*)g_P : (float*)g_Xa;

    const int tid = threadIdx.x;
    const int trow = tid >> 4;
    const int tcol = tid & 15;
    const int m0 = blockIdx.y * 128;
    const int n0 = blockIdx.x * 64;

    unsigned long long acc01[8], acc23[8];
#pragma unroll
    for (int i = 0; i < 8; i++) { acc01[i] = 0ULL; acc23[i] = 0ULL; }

    for (int k0 = 0; k0 < K; k0 += 16) {
#pragma unroll
        for (int p = 0; p < 2; p++) {
            int i = tid + p * 256;
            int m = i >> 2;
            int kq = (i & 3) * 4;
            float4 v = *(const float4*)&Amat[(long)(m0 + m) * K + k0 + kq];
            As[kq + 0][m] = v.x;
            As[kq + 1][m] = v.y;
            As[kq + 2][m] = v.z;
            As[kq + 3][m] = v.w;
        }
        {
            int k = tid >> 4;
            int nq = (tid & 15) * 4;
            *(float4*)&Bs[k][nq] = *(const float4*)&B[(long)(k0 + k) * N + n0 + nq];
        }
        __syncthreads();

#pragma unroll
        for (int kk = 0; kk < 16; kk++) {
            float a0[8];
            float4 av0 = *(float4*)&As[kk][trow * 8];
            float4 av1 = *(float4*)&As[kk][trow * 8 + 4];
            a0[0] = av0.x; a0[1] = av0.y; a0[2] = av0.z; a0[3] = av0.w;
            a0[4] = av1.x; a0[5] = av1.y; a0[6] = av1.z; a0[7] = av1.w;
            ulonglong2 bv = *(ulonglong2*)&Bs[kk][tcol * 4];
#pragma unroll
            for (int i = 0; i < 8; i++) {
                unsigned long long ad = dup2(a0[i]);
                acc01[i] = fma2(ad, bv.x, acc01[i]);
                acc23[i] = fma2(ad, bv.y, acc23[i]);
            }
        }
        __syncthreads();
    }

#pragma unroll
    for (int i = 0; i < 8; i++) {
        int row = m0 + trow * 8 + i;
        int colb = n0 + tcol * 4;
        float2 a01 = unpack2(acc01[i]);
        float2 a23 = unpack2(acc23[i]);
        if (MODE == 0) {
            float4 bv = *(const float4*)&bias[colb];
            float4 o;
            o.x = a01.x + bv.x;
            o.y = a01.y + bv.y;
            o.z = a23.x + bv.z;
            o.w = a23.y + bv.w;
            *(float4*)&C[(long)row * N + colb] = o;
        } else {
            float av[4] = {a01.x, a01.y, a23.x, a23.y};
#pragma unroll
            for (int j = 0; j < 4; j++) {
                int col = colb + j;
                int g = col >> 10;
                int cl = col & 1023;
                C[((long)row * 1024 + cl) * 4 + g] = av[j];
            }
        }
    }
}

// ---------------- init: h0 = c0 = mean(Af), scores0 = h0·Af ----------------
__global__ void __launch_bounds__(256) init_kernel(const float* __restrict__ A) {
    const int n = blockIdx.x;
    const int tid = threadIdx.x;
    __shared__ float sc[256][16];

    float accl[16];
#pragma unroll
    for (int l = 0; l < 16; l++) accl[l] = 0.0f;

    for (int h = tid; h < HH; h += 256) {
        const float* ar = A + ((n << 10) + h) * 16;
        float a[16];
        float4 v0 = *(const float4*)&ar[0];
        float4 v1 = *(const float4*)&ar[4];
        float4 v2 = *(const float4*)&ar[8];
        float4 v3 = *(const float4*)&ar[12];
        a[0]=v0.x; a[1]=v0.y; a[2]=v0.z; a[3]=v0.w;
        a[4]=v1.x; a[5]=v1.y; a[6]=v1.z; a[7]=v1.w;
        a[8]=v2.x; a[9]=v2.y; a[10]=v2.z; a[11]=v2.w;
        a[12]=v3.x; a[13]=v3.y; a[14]=v3.z; a[15]=v3.w;
        float s = 0.0f;
#pragma unroll
        for (int l = 0; l < 16; l++) s += a[l];
        s *= (1.0f / 16.0f);
        g_hdup[0][(n << 10) + h] = make_float2(s, s);
        g_cbuf[0][(n << 10) + h] = s;
#pragma unroll
        for (int l = 0; l < 16; l++) accl[l] += s * a[l];
    }
#pragma unroll
    for (int l = 0; l < 16; l++) sc[tid][l] = accl[l];
    __syncthreads();
    if (tid < 16) {
        float s = 0.0f;
        for (int j = 0; j < 256; j++) s += sc[j][tid];
        g_scores[0][n * 16 + tid] = s;
        g_scores[1][n * 16 + tid] = 0.0f;
        g_scores[2][n * 16 + tid] = 0.0f;
    }
}

// ---------------- fused step: 512 threads, BK=64, 3-stage cp.async ----------
// CTA (cb, nb): gate-cols cb*16..+16, batch rows nb*32..+32. 1 n per thread.
// Dynamic smem layout (bytes):
//   sW : 3 * 64 * 16 * 16  = 49152   [buf][k][tx] -> ulonglong2 (4 gate wts)
//   sH : 3 * 32 * 64 * 8   = 49152   [buf][n][k]  -> float2 (h,h)
//   ws : 32 * 16 * 4       = 2048
//   sred : 512 * 4         = 2048
#define STP_SW   0
#define STP_SH   49152
#define STP_WS   (49152 + 49152)
#define STP_SRED (49152 + 49152 + 2048)
#define STP_TOT  (49152 + 49152 + 2048 + 2048)

__global__ void __launch_bounds__(512, 1) step_kernel(int t, const float* __restrict__ A,
                                                      float* __restrict__ out) {
    extern __shared__ char smem[];
    ulonglong2* sW = (ulonglong2*)(smem + STP_SW);   // [3][64][16]
    float2*     sH = (float2*)(smem + STP_SH);       // [3][32][64]
    float*      ws = (float*)(smem + STP_WS);        // [32][16]
    float*      sred = (float*)(smem + STP_SRED);    // [512]

    const int tid = threadIdx.x;
    const int tx = tid & 15;          // gate-col within CTA
    const int ny = tid >> 4;          // 0..31, one n each
    const int cb = blockIdx.x;        // 0..63
    const int nb = blockIdx.y;        // 0..1
    const int cb16 = cb * 16;
    const int nb32 = nb * 32;
    const int c = cb16 + tx;
    const int n = nb32 + ny;

    const int prev = t & 1;
    const int cur = prev ^ 1;
    const float2* hsrc = g_hdup[prev];
    const float* c_prev = g_cbuf[prev];
    const float* sc_in = g_scores[t % 3];
    float* sc_out  = g_scores[(t + 1) % 3];
    float* sc_zero = g_scores[(t + 2) % 3];

#define STAGE(kb_, b_) do {                                                     \
        int k0_ = (kb_) << 6;                                                   \
        _Pragma("unroll")                                                       \
        for (int j_ = 0; j_ < 2; j_++) {                                        \
            int i_ = tid + j_ * 512;                                            \
            int kl_ = i_ >> 4, txi_ = i_ & 15;                                  \
            cp_async16(smem_u32(&sW[((b_) * 64 + kl_) * 16 + txi_]),            \
                       &((const float4*)g_WhT)[(k0_ + kl_) * 1024 + cb16 + txi_]); \
        }                                                                       \
        _Pragma("unroll")                                                       \
        for (int j_ = 0; j_ < 2; j_++) {                                        \
            int i_ = tid + j_ * 512;                                            \
            int nl_ = i_ >> 5, kq_ = (i_ & 31) * 2;                             \
            cp_async16(smem_u32(&sH[((b_) * 32 + nl_) * 64 + kq_]),             \
                       &hsrc[((nb32 + nl_) << 10) + k0_ + kq_]);                \
        }                                                                       \
        asm volatile("cp.async.commit_group;" ::: "memory");                    \
    } while (0)

    // prefetch chunks 0,1
    STAGE(0, 0);
    STAGE(1, 1);

    // redundant per-CTA softmax over its 32 rows
    if (tid < 32) {
        float s[16];
        float m = -1e30f;
#pragma unroll
        for (int l = 0; l < 16; l++) {
            s[l] = sc_in[(nb32 + tid) * 16 + l] * 0.03125f;  // 1/sqrt(1024)
            m = fmaxf(m, s[l]);
        }
        float sum = 0.0f;
#pragma unroll
        for (int l = 0; l < 16; l++) { s[l] = expf(s[l] - m); sum += s[l]; }
        float inv = 1.0f / sum;
#pragma unroll
        for (int l = 0; l < 16; l++) ws[tid * 16 + l] = s[l] * inv;
    }
    // zero the score buffer for step t+1 (128 CTAs x 8 entries = 1024)
    if (tid < 8) sc_zero[(nb * 64 + cb) * 8 + tid] = 0.0f;

    // acc init from Xa (bias folded in)
    unsigned long long a01, a23;
    {
        const float* xa = g_Xa + (long)(n * TT + t) * G4 + c;
        a01 = pack2(xa[0], xa[1024]);
        a23 = pack2(xa[2048], xa[3072]);
    }

    // main recurrent GEMM: 16 chunks of 64 k, 3-stage pipeline
    for (int kb = 0; kb < 16; kb++) {
        if (kb < 15) asm volatile("cp.async.wait_group 1;" ::: "memory");
        else         asm volatile("cp.async.wait_group 0;" ::: "memory");
        __syncthreads();
        if (kb < 14) STAGE(kb + 2, (kb + 2) % 3);

        const int b = kb % 3;
        const float2* hrow = &sH[(b * 32 + ny) * 64];
        const ulonglong2* wrow = &sW[(b * 64) * 16 + tx];
#pragma unroll 16
        for (int kk = 0; kk < 64; kk += 2) {
            ulonglong2 hq = *(const ulonglong2*)&hrow[kk];   // (h_kk,h_kk),(h_kk1,h_kk1)
            ulonglong2 w0 = wrow[kk * 16];
            ulonglong2 w1 = wrow[(kk + 1) * 16];
            a01 = fma2(hq.x, w0.x, a01);
            a23 = fma2(hq.x, w0.y, a23);
            a01 = fma2(hq.y, w1.x, a01);
            a23 = fma2(hq.y, w1.y, a23);
        }
    }

    // attention term: a += w @ P (P packed [n][l][c][gate])
    const ulonglong2* Pu = (const ulonglong2*)g_P;
#pragma unroll
    for (int l = 0; l < 16; l++) {
        unsigned long long wv = dup2(ws[ny * 16 + l]);
        ulonglong2 p = Pu[(n * 16 + l) * 1024 + c];
        a01 = fma2(wv, p.x, a01);
        a23 = fma2(wv, p.y, a23);
    }

    // LSTM epilogue
    float2 A01 = unpack2(a01), A23 = unpack2(a23);
    float ig = 1.0f / (1.0f + expf(-A01.x));
    float fg = 1.0f / (1.0f + expf(-A01.y));
    float og = 1.0f / (1.0f + expf(-A23.x));
    float gg = tanhf(A23.y);
    float cp = c_prev[(n << 10) + c];
    float cn = fg * cp + ig * gg;
    float h = og * tanhf(cn);
    g_cbuf[cur][(n << 10) + c] = cn;
    g_hdup[cur][(n << 10) + c] = make_float2(h, h);
    out[(long)(n * TT + t) * HH + c] = h;

    // next-step score partials: scores[n][l] += sum_c h*A[n][c][l]
    {
        const float* ar = A + ((long)(n << 10) + c) * 16;
        float a[16];
        float4 v0 = *(const float4*)&ar[0];
        float4 v1 = *(const float4*)&ar[4];
        float4 v2 = *(const float4*)&ar[8];
        float4 v3 = *(const float4*)&ar[12];
        a[0]=v0.x; a[1]=v0.y; a[2]=v0.z; a[3]=v0.w;
        a[4]=v1.x; a[5]=v1.y; a[6]=v1.z; a[7]=v1.w;
        a[8]=v2.x; a[9]=v2.y; a[10]=v2.z; a[11]=v2.w;
        a[12]=v3.x; a[13]=v3.y; a[14]=v3.z; a[15]=v3.w;
#pragma unroll
        for (int l = 0; l < 16; l++) {
            float v = h * a[l];
            v += __shfl_xor_sync(0xffffffffu, v, 1);
            v += __shfl_xor_sync(0xffffffffu, v, 2);
            v += __shfl_xor_sync(0xffffffffu, v, 4);
            v += __shfl_xor_sync(0xffffffffu, v, 8);
            if (tx == 0) sred[ny * 16 + l] = v;
        }
    }
    __syncthreads();
    atomicAdd(&sc_out[nb * 512 + tid], sred[tid]);
#undef STAGE
}

// ---------------- launcher ----------------
extern "C" void kernel_launch(void* const* d_in, const int* in_sizes, int n_in,
                              void* d_out, int out_size) {
    const float* x     = (const float*)d_in[0];
    const float* A     = (const float*)d_in[1];
    const float* Wx    = (const float*)d_in[2];
    const float* Wh    = (const float*)d_in[3];
    const float* Wattn = (const float*)d_in[4];
    const float* b     = (const float*)d_in[5];
    float* out = (float*)d_out;

    cudaFuncSetAttribute(step_kernel, cudaFuncAttributeMaxDynamicSharedMemorySize,
                         STP_TOT);

    pack_wh_kernel<<<4096, 256>>>(Wh);
    transposeA_kernel<<<4096, 256>>>(A);
    // Xa = x @ Wx + b : M=8192, N=4096, K=512
    sgemm_kernel<0><<<dim3(G4 / 64, (NN * TT) / 128), 256>>>(x, Wx, b, NN * TT, G4, DD);
    // P = A2 @ Wattn  : M=1024, N=4096, K=1024 (packed output)
    sgemm_kernel<1><<<dim3(G4 / 64, (NN * 16) / 128), 256>>>(nullptr, Wattn, nullptr,
                                                             NN * 16, G4, HH);
    init_kernel<<<NN, 256>>>(A);

    // sequential recurrence: one fused kernel per timestep
    for (int t = 0; t < TT; t++) {
        step_kernel<<<dim3(64, 2), 512, STP_TOT>>>(t, A, out);
    }
}

// round 8
// speedup vs baseline: 1.5392x; 1.5392x over previous
#include <cuda_runtime.h>
#include <math.h>
#include <stdint.h>

// Problem constants
#define NN 64
#define TT 128
#define DD 512
#define HH 1024
#define G4 4096   // 4*H

// ---------------- scratch (device globals; no allocations) ----------------
__device__ __align__(16) float  g_Xa[(NN * TT) * G4];   // 128 MB: x@Wx + b
__device__ __align__(16) float  g_P[(NN * 16) * G4];    // 16 MB: packed [n][l][c][gate]
__device__ __align__(16) float  g_WhT[HH * G4];         // 16 MB: packed [k][c][gate]
__device__ __align__(16) float  g_A2[(NN * 16) * HH];   // 4 MB
__device__ __align__(16) float2 g_hT[2][HH * NN];       // h dup (h,h), [parity][k][n]
__device__ float g_cbuf[2][NN * HH];
__device__ float g_scores[3][NN * 16];

// ---------------- helpers ----------------
__device__ __forceinline__ unsigned long long fma2(unsigned long long a,
                                                   unsigned long long b,
                                                   unsigned long long c) {
    unsigned long long d;
    asm("fma.rn.f32x2 %0, %1, %2, %3;" : "=l"(d) : "l"(a), "l"(b), "l"(c));
    return d;
}
__device__ __forceinline__ unsigned long long add2(unsigned long long a,
                                                   unsigned long long b) {
    unsigned long long d;
    asm("add.rn.f32x2 %0, %1, %2;" : "=l"(d) : "l"(a), "l"(b));
    return d;
}
__device__ __forceinline__ unsigned long long dup2(float v) {
    unsigned long long r;
    asm("mov.b64 %0, {%1, %1};" : "=l"(r) : "f"(v));
    return r;
}
__device__ __forceinline__ float2 unpack2(unsigned long long v) {
    float2 f;
    asm("mov.b64 {%0, %1}, %2;" : "=f"(f.x), "=f"(f.y) : "l"(v));
    return f;
}
__device__ __forceinline__ uint32_t smem_u32(const void* p) {
    return (uint32_t)__cvta_generic_to_shared(p);
}
__device__ __forceinline__ void cp_async16(uint32_t dst, const void* src) {
    asm volatile("cp.async.cg.shared.global [%0], [%1], 16;" :: "r"(dst), "l"(src) : "memory");
}

// ---------------- weight packing ----------------
__global__ void __launch_bounds__(256) pack_wh_kernel(const float* __restrict__ Wh) {
    int idx = blockIdx.x * 256 + threadIdx.x;
    int k = idx >> 10;
    int c = idx & 1023;
    const float* row = Wh + k * G4;
    float4 v;
    v.x = row[c];
    v.y = row[1024 + c];
    v.z = row[2048 + c];
    v.w = row[3072 + c];
    *(float4*)&g_WhT[idx * 4] = v;
}

__global__ void __launch_bounds__(256) transposeA_kernel(const float* __restrict__ A) {
    int idx = blockIdx.x * 256 + threadIdx.x;
    int r = idx >> 10;
    int k = idx & 1023;
    int n = r >> 4;
    int l = r & 15;
    g_A2[idx] = A[((n << 10) + k) * 16 + l];
}

// ---------------- tiled SGEMM (unchanged) ----------------
template <int MODE>
__global__ void __launch_bounds__(256) sgemm_kernel(const float* __restrict__ Ain,
                                                    const float* __restrict__ B,
                                                    const float* __restrict__ bias,
                                                    int M, int N, int K) {
    __shared__ float As[16][128];
    __shared__ float Bs[16][64];

    const float* Amat = (MODE == 1) ? (const float*)g_A2 : Ain;
    float* C = (MODE == 1) ? (float*)g_P : (float*)g_Xa;

    const int tid = threadIdx.x;
    const int trow = tid >> 4;
    const int tcol = tid & 15;
    const int m0 = blockIdx.y * 128;
    const int n0 = blockIdx.x * 64;

    unsigned long long acc01[8], acc23[8];
#pragma unroll
    for (int i = 0; i < 8; i++) { acc01[i] = 0ULL; acc23[i] = 0ULL; }

    for (int k0 = 0; k0 < K; k0 += 16) {
#pragma unroll
        for (int p = 0; p < 2; p++) {
            int i = tid + p * 256;
            int m = i >> 2;
            int kq = (i & 3) * 4;
            float4 v = *(const float4*)&Amat[(long)(m0 + m) * K + k0 + kq];
            As[kq + 0][m] = v.x;
            As[kq + 1][m] = v.y;
            As[kq + 2][m] = v.z;
            As[kq + 3][m] = v.w;
        }
        {
            int k = tid >> 4;
            int nq = (tid & 15) * 4;
            *(float4*)&Bs[k][nq] = *(const float4*)&B[(long)(k0 + k) * N + n0 + nq];
        }
        __syncthreads();

#pragma unroll
        for (int kk = 0; kk < 16; kk++) {
            float a0[8];
            float4 av0 = *(float4*)&As[kk][trow * 8];
            float4 av1 = *(float4*)&As[kk][trow * 8 + 4];
            a0[0] = av0.x; a0[1] = av0.y; a0[2] = av0.z; a0[3] = av0.w;
            a0[4] = av1.x; a0[5] = av1.y; a0[6] = av1.z; a0[7] = av1.w;
            ulonglong2 bv = *(ulonglong2*)&Bs[kk][tcol * 4];
#pragma unroll
            for (int i = 0; i < 8; i++) {
                unsigned long long ad = dup2(a0[i]);
                acc01[i] = fma2(ad, bv.x, acc01[i]);
                acc23[i] = fma2(ad, bv.y, acc23[i]);
            }
        }
        __syncthreads();
    }

#pragma unroll
    for (int i = 0; i < 8; i++) {
        int row = m0 + trow * 8 + i;
        int colb = n0 + tcol * 4;
        float2 a01 = unpack2(acc01[i]);
        float2 a23 = unpack2(acc23[i]);
        if (MODE == 0) {
            float4 bv = *(const float4*)&bias[colb];
            float4 o;
            o.x = a01.x + bv.x;
            o.y = a01.y + bv.y;
            o.z = a23.x + bv.z;
            o.w = a23.y + bv.w;
            *(float4*)&C[(long)row * N + colb] = o;
        } else {
            float av[4] = {a01.x, a01.y, a23.x, a23.y};
#pragma unroll
            for (int j = 0; j < 4; j++) {
                int col = colb + j;
                int g = col >> 10;
                int cl = col & 1023;
                C[((long)row * 1024 + cl) * 4 + g] = av[j];
            }
        }
    }
}

// ---------------- init: h0 = c0 = mean(Af), scores0 = h0·Af ----------------
__global__ void __launch_bounds__(256) init_kernel(const float* __restrict__ A) {
    const int n = blockIdx.x;
    const int tid = threadIdx.x;
    __shared__ float sc[256][16];

    float accl[16];
#pragma unroll
    for (int l = 0; l < 16; l++) accl[l] = 0.0f;

    for (int h = tid; h < HH; h += 256) {
        const float* ar = A + ((n << 10) + h) * 16;
        float a[16];
        float4 v0 = *(const float4*)&ar[0];
        float4 v1 = *(const float4*)&ar[4];
        float4 v2 = *(const float4*)&ar[8];
        float4 v3 = *(const float4*)&ar[12];
        a[0]=v0.x; a[1]=v0.y; a[2]=v0.z; a[3]=v0.w;
        a[4]=v1.x; a[5]=v1.y; a[6]=v1.z; a[7]=v1.w;
        a[8]=v2.x; a[9]=v2.y; a[10]=v2.z; a[11]=v2.w;
        a[12]=v3.x; a[13]=v3.y; a[14]=v3.z; a[15]=v3.w;
        float s = 0.0f;
#pragma unroll
        for (int l = 0; l < 16; l++) s += a[l];
        s *= (1.0f / 16.0f);
        g_hT[0][(h << 6) + n] = make_float2(s, s);   // transposed [k][n], dup
        g_cbuf[0][(n << 10) + h] = s;
#pragma unroll
        for (int l = 0; l < 16; l++) accl[l] += s * a[l];
    }
#pragma unroll
    for (int l = 0; l < 16; l++) sc[tid][l] = accl[l];
    __syncthreads();
    if (tid < 16) {
        float s = 0.0f;
        for (int j = 0; j < 256; j++) s += sc[j][tid];
        g_scores[0][n * 16 + tid] = s;
        g_scores[1][n * 16 + tid] = 0.0f;
        g_scores[2][n * 16 + tid] = 0.0f;
    }
}

// ---------------- fused step: warp-k-split, 16 n/thread, partial reduction --
// CTA (cb, nb): 16 gate-cols (cb*16..), 32 batch rows (nb*32..). 256 threads.
// Warp w (0..7) owns k-slice w*16..+16 of each 128-k chunk; lane = (tx, ny):
// tx = gate-col, ny*16.. = 16 batch rows per thread. 32 u64 f32x2 accumulators.
// After the k-loop: smem partial reduction (overlaying the weight stages),
// then per-cell epilogue (Xa + LSTM + h/c/out/score writes).
// SMEM: sW 3x32KB | sH 3x32KB | ws 2KB     (part[8][1024] u64 overlays sW)
#define STP_SW   0
#define STP_SH   98304
#define STP_WS   196608
#define STP_TOT  (196608 + 2048)

__global__ void __launch_bounds__(256, 1) step_kernel(int t, const float* __restrict__ A,
                                                      float* __restrict__ out) {
    extern __shared__ char smem[];
    ulonglong2* sWu = (ulonglong2*)(smem + STP_SW);   // [3][128k][16c]
    ulonglong2* sHu = (ulonglong2*)(smem + STP_SH);   // [3][128k][8 npair2]
    float*      ws  = (float*)(smem + STP_WS);        // [32 n][16 l]

    const int tid  = threadIdx.x;
    const int lane = tid & 31;
    const int wid  = tid >> 5;       // 0..7 : k-slice within chunk
    const int tx   = lane & 15;      // gate-col within CTA
    const int ny   = lane >> 4;      // 0/1 : 16-row half
    const int cb   = blockIdx.x;     // 0..63
    const int nb   = blockIdx.y;     // 0..1
    const int cb16 = cb * 16;
    const int nb32 = nb * 32;

    const int prev = t & 1;
    const int cur  = prev ^ 1;
    const float2* hsrc = g_hT[prev];
    const float* sc_in = g_scores[t % 3];
    float* sc_out  = g_scores[(t + 1) % 3];
    float* sc_zero = g_scores[(t + 2) % 3];

#define STAGE(q_, b_) do {                                                      \
        int k0_ = (q_) << 7;                                                    \
        _Pragma("unroll")                                                       \
        for (int j_ = 0; j_ < 8; j_++) {                                        \
            int s_ = tid + j_ * 256;            /* 0..2047 */                   \
            int kl_ = s_ >> 4, xi_ = s_ & 15;                                   \
            cp_async16(smem_u32(&sWu[(b_) * 2048 + s_]),                        \
                       &((const float4*)g_WhT)[(k0_ + kl_) * 1024 + cb16 + xi_]); \
            cp_async16(smem_u32(&sHu[(b_) * 2048 + s_]),                        \
                       &hsrc[((k0_ + kl_) << 6) + nb32 + xi_ * 2]);             \
        }                                                                       \
        asm volatile("cp.async.commit_group;" ::: "memory");                    \
    } while (0)

    STAGE(0, 0);
    STAGE(1, 1);

    // redundant per-CTA softmax over its 32 rows
    if (tid < 32) {
        float s[16];
        float m = -1e30f;
#pragma unroll
        for (int l = 0; l < 16; l++) {
            s[l] = sc_in[(nb32 + tid) * 16 + l] * 0.03125f;  // 1/sqrt(1024)
            m = fmaxf(m, s[l]);
        }
        float sum = 0.0f;
#pragma unroll
        for (int l = 0; l < 16; l++) { s[l] = expf(s[l] - m); sum += s[l]; }
        float inv = 1.0f / sum;
#pragma unroll
        for (int l = 0; l < 16; l++) ws[tid * 16 + l] = s[l] * inv;
    }
    // zero the score buffer for step t+1 (128 CTAs x 8 entries = 1024)
    if (tid < 8) sc_zero[(nb * 64 + cb) * 8 + tid] = 0.0f;
    __syncthreads();

    // 32 partial accumulators (16 n x 2 gate-pairs), start at zero
    unsigned long long a01[16], a23[16];
#pragma unroll
    for (int j = 0; j < 16; j++) { a01[j] = 0ULL; a23[j] = 0ULL; }

    // attention term folded into partials: warp wid handles l = 2*wid, 2*wid+1
    {
        const ulonglong2* Pu = (const ulonglong2*)g_P;
#pragma unroll
        for (int li = 0; li < 2; li++) {
            int l = wid * 2 + li;
#pragma unroll
            for (int j = 0; j < 16; j++) {
                int nl = ny * 16 + j;
                unsigned long long wv = dup2(ws[nl * 16 + l]);
                ulonglong2 p = Pu[(((nb32 + nl) * 16 + l) << 10) + cb16 + tx];
                a01[j] = fma2(wv, p.x, a01[j]);
                a23[j] = fma2(wv, p.y, a23[j]);
            }
        }
    }

    // main recurrent GEMM: 8 chunks of 128 k; warp owns rows wid*16..+16
    for (int q = 0; q < 8; q++) {
        if (q < 7) asm volatile("cp.async.wait_group 1;" ::: "memory");
        else       asm volatile("cp.async.wait_group 0;" ::: "memory");
        __syncthreads();
        if (q < 6) STAGE(q + 2, (q + 2) % 3);

        const int b = q % 3;
        const ulonglong2* wrow = &sWu[b * 2048 + (wid * 16) * 16 + tx];
        const ulonglong2* hrow = &sHu[b * 2048 + (wid * 16) * 16 + ny * 8];
#pragma unroll 2
        for (int kk = 0; kk < 16; kk++) {
            ulonglong2 w = wrow[kk * 16];
#pragma unroll
            for (int i = 0; i < 8; i++) {
                ulonglong2 hq = hrow[kk * 16 + i];   // dup pairs for n=2i,2i+1
                a01[2 * i]     = fma2(hq.x, w.x, a01[2 * i]);
                a23[2 * i]     = fma2(hq.x, w.y, a23[2 * i]);
                a01[2 * i + 1] = fma2(hq.y, w.x, a01[2 * i + 1]);
                a23[2 * i + 1] = fma2(hq.y, w.y, a23[2 * i + 1]);
            }
        }
    }
    __syncthreads();

    // write partials to smem (overlaying dead weight stages)
    unsigned long long* part = (unsigned long long*)smem;   // [8][1024]
#pragma unroll
    for (int j = 0; j < 16; j++) {
        int cell = ((ny * 16 + j) * 16 + tx) * 2;
        part[wid * 1024 + cell]     = a01[j];
        part[wid * 1024 + cell + 1] = a23[j];
    }
    __syncthreads();

    // cross-warp reduction: 4 u64 outputs per thread = 2 cells
    unsigned long long r0 = part[tid * 4 + 0];
    unsigned long long r1 = part[tid * 4 + 1];
    unsigned long long r2 = part[tid * 4 + 2];
    unsigned long long r3 = part[tid * 4 + 3];
#pragma unroll
    for (int w = 1; w < 8; w++) {
        ulonglong2 pa = *(const ulonglong2*)&part[w * 1024 + tid * 4];
        ulonglong2 pb = *(const ulonglong2*)&part[w * 1024 + tid * 4 + 2];
        r0 = add2(r0, pa.x);
        r1 = add2(r1, pa.y);
        r2 = add2(r2, pb.x);
        r3 = add2(r3, pb.y);
    }

    // epilogue: cells (n, c0) and (n, c1) where c1 = c0+1
    const int nl = tid >> 3;             // 0..31
    const int c0 = (tid & 7) * 2;
    const int n  = nb32 + nl;
    const int cg0 = cb16 + c0;
    const int cg1 = cg0 + 1;

    const float* xa = g_Xa + (long)(n * TT + t) * G4;
    float2 A01_0 = unpack2(r0), A23_0 = unpack2(r1);
    float2 A01_1 = unpack2(r2), A23_1 = unpack2(r3);
    A01_0.x += xa[cg0];        A01_0.y += xa[1024 + cg0];
    A23_0.x += xa[2048 + cg0]; A23_0.y += xa[3072 + cg0];
    A01_1.x += xa[cg1];        A01_1.y += xa[1024 + cg1];
    A23_1.x += xa[2048 + cg1]; A23_1.y += xa[3072 + cg1];

    float ig0 = 1.0f / (1.0f + expf(-A01_0.x));
    float fg0 = 1.0f / (1.0f + expf(-A01_0.y));
    float og0 = 1.0f / (1.0f + expf(-A23_0.x));
    float gg0 = tanhf(A23_0.y);
    float cp0 = g_cbuf[prev][(n << 10) + cg0];
    float cn0 = fg0 * cp0 + ig0 * gg0;
    float h0 = og0 * tanhf(cn0);

    float ig1 = 1.0f / (1.0f + expf(-A01_1.x));
    float fg1 = 1.0f / (1.0f + expf(-A01_1.y));
    float og1 = 1.0f / (1.0f + expf(-A23_1.x));
    float gg1 = tanhf(A23_1.y);
    float cp1 = g_cbuf[prev][(n << 10) + cg1];
    float cn1 = fg1 * cp1 + ig1 * gg1;
    float h1 = og1 * tanhf(cn1);

    g_cbuf[cur][(n << 10) + cg0] = cn0;
    g_cbuf[cur][(n << 10) + cg1] = cn1;
    g_hT[cur][(cg0 << 6) + n] = make_float2(h0, h0);
    g_hT[cur][(cg1 << 6) + n] = make_float2(h1, h1);
    *(float2*)&out[(long)(n * TT + t) * HH + cg0] = make_float2(h0, h1);

    // next-step score partials: reduce over 16 c (8 threads x 2 c) via shfl
    {
        const float* ar0 = A + ((long)(n << 10) + cg0) * 16;
        const float* ar1 = A + ((long)(n << 10) + cg1) * 16;
        float a0[16], a1[16];
#pragma unroll
        for (int v = 0; v < 4; v++) {
            float4 q0 = *(const float4*)&ar0[v * 4];
            float4 q1 = *(const float4*)&ar1[v * 4];
            a0[v*4+0]=q0.x; a0[v*4+1]=q0.y; a0[v*4+2]=q0.z; a0[v*4+3]=q0.w;
            a1[v*4+0]=q1.x; a1[v*4+1]=q1.y; a1[v*4+2]=q1.z; a1[v*4+3]=q1.w;
        }
#pragma unroll
        for (int l = 0; l < 16; l++) {
            float v = h0 * a0[l] + h1 * a1[l];
            v += __shfl_xor_sync(0xffffffffu, v, 1);
            v += __shfl_xor_sync(0xffffffffu, v, 2);
            v += __shfl_xor_sync(0xffffffffu, v, 4);
            if ((lane & 7) == 0) atomicAdd(&sc_out[n * 16 + l], v);
        }
    }
#undef STAGE
}

// ---------------- launcher ----------------
extern "C" void kernel_launch(void* const* d_in, const int* in_sizes, int n_in,
                              void* d_out, int out_size) {
    const float* x     = (const float*)d_in[0];
    const float* A     = (const float*)d_in[1];
    const float* Wx    = (const float*)d_in[2];
    const float* Wh    = (const float*)d_in[3];
    const float* Wattn = (const float*)d_in[4];
    const float* b     = (const float*)d_in[5];
    float* out = (float*)d_out;

    cudaFuncSetAttribute(step_kernel, cudaFuncAttributeMaxDynamicSharedMemorySize,
                         STP_TOT);

    pack_wh_kernel<<<4096, 256>>>(Wh);
    transposeA_kernel<<<4096, 256>>>(A);
    // Xa = x @ Wx + b : M=8192, N=4096, K=512
    sgemm_kernel<0><<<dim3(G4 / 64, (NN * TT) / 128), 256>>>(x, Wx, b, NN * TT, G4, DD);
    // P = A2 @ Wattn  : M=1024, N=4096, K=1024 (packed output)
    sgemm_kernel<1><<<dim3(G4 / 64, (NN * 16) / 128), 256>>>(nullptr, Wattn, nullptr,
                                                             NN * 16, G4, HH);
    init_kernel<<<NN, 256>>>(A);

    // sequential recurrence: one fused kernel per timestep
    for (int t = 0; t < TT; t++) {
        step_kernel<<<dim3(64, 2), 256, STP_TOT>>>(t, A, out);
    }
}